// round 1
// baseline (speedup 1.0000x reference)
#include <cuda_runtime.h>
#include <math.h>

// ---------------- problem constants ----------------
constexpr int BB   = 32;
constexpr int NSEQ = 256;
constexpr int DIM  = 1024;
constexpr int NH   = 16;
constexpr int HDIM = 64;
constexpr int CDIM = 1024;
constexpr int NE   = 4;
constexpr int DFFC = 4096;
constexpr int RHC  = 2048;
constexpr int TT   = BB * NSEQ;   // 8192 tokens

// ---------------- scratch (device globals; no allocation allowed) ----------------
__device__ float g_h1[TT * DIM];
__device__ float g_qkv[TT * 3 * DIM];
__device__ float g_S[(size_t)BB * NH * NSEQ * NSEQ];
__device__ float g_o[TT * DIM];
__device__ float g_x1[TT * DIM];
__device__ float g_h2[TT * DIM];
__device__ float g_condc[BB * RHC];
__device__ float g_gh[(size_t)TT * RHC];
__device__ float g_hid[(size_t)TT * DFFC];
__device__ int   g_cnt[NE];
__device__ int   g_idx[NE * TT];
__device__ float g_wgt[NE * TT];

// ---------------- helpers ----------------
__device__ __forceinline__ float warpsum(float v) {
    #pragma unroll
    for (int o = 16; o; o >>= 1) v += __shfl_xor_sync(0xFFFFFFFFu, v, o);
    return v;
}
__device__ __forceinline__ float warpmax(float v) {
    #pragma unroll
    for (int o = 16; o; o >>= 1) v = fmaxf(v, __shfl_xor_sync(0xFFFFFFFFu, v, o));
    return v;
}
__device__ __forceinline__ float gelu_f(float x) {
    return 0.5f * x * (1.0f + erff(x * 0.70710678118654752f));
}

// ---------------- LayerNorm: one block per token, 256 threads ----------------
__global__ __launch_bounds__(256) void ln_kernel(
    const float* __restrict__ x, const float* __restrict__ g,
    const float* __restrict__ bta, float* __restrict__ out)
{
    int t = blockIdx.x, tid = threadIdx.x;
    float4 v = ((const float4*)(x + (size_t)t * DIM))[tid];
    float s  = v.x + v.y + v.z + v.w;
    float sq = v.x * v.x + v.y * v.y + v.z * v.z + v.w * v.w;
    __shared__ float sh[8], sh2[8];
    float ws = warpsum(s), wq = warpsum(sq);
    if ((tid & 31) == 0) { sh[tid >> 5] = ws; sh2[tid >> 5] = wq; }
    __syncthreads();
    if (tid < 32) {
        float a  = (tid < 8) ? sh[tid]  : 0.f;
        float b2 = (tid < 8) ? sh2[tid] : 0.f;
        a = warpsum(a); b2 = warpsum(b2);
        if (tid == 0) { sh[0] = a; sh2[0] = b2; }
    }
    __syncthreads();
    float mu  = sh[0] * (1.0f / DIM);
    float var = sh2[0] * (1.0f / DIM) - mu * mu;
    float inv = rsqrtf(var + 1e-5f);
    float4 gg = ((const float4*)g)[tid], bb = ((const float4*)bta)[tid];
    float4 o;
    o.x = (v.x - mu) * inv * gg.x + bb.x;
    o.y = (v.y - mu) * inv * gg.y + bb.y;
    o.z = (v.z - mu) * inv * gg.z + bb.z;
    o.w = (v.w - mu) * inv * gg.w + bb.w;
    ((float4*)(out + (size_t)t * DIM))[tid] = o;
}

// ---------------- generic SGEMM 128x128x8, 256 thr, 8x8/thread ----------------
// C[M,Nn] = A[M,K] @ B[K,Nn]  row-major; N multiple of 128, K multiple of 8.
// GATHER:   A row r comes from gidx[r]
// SCATTER:  C[gidx[r]] += wrow[r] * val   (otherwise C[r] = val)
// BIAS/CONDC/GELU/RESID epilogue (order: +bias, +condc[row>>8], gelu, +res)
template<bool GATHER, bool SCATTER, bool BIAS, bool GELU, bool RESID, bool CONDC>
__global__ __launch_bounds__(256) void gemm_kernel(
    const float* __restrict__ A, const float* __restrict__ Bm, float* __restrict__ C,
    int M, int Nn, int K,
    const float* __restrict__ bias, const float* __restrict__ res,
    const float* __restrict__ condc,
    const int* __restrict__ gidx, const float* __restrict__ wrow,
    const int* __restrict__ cntp)
{
    if (cntp) M = *cntp;
    int row0 = blockIdx.y * 128;
    if (row0 >= M) return;
    int col0 = blockIdx.x * 128;

    __shared__ float As[8][128];
    __shared__ float Bs[8][128];

    int tid = threadIdx.x;
    int arid = tid >> 1;
    int akq  = (tid & 1) * 4;
    int arow_t = row0 + arid;
    bool avalid = arow_t < M;
    int arow = avalid ? (GATHER ? gidx[arow_t] : arow_t) : 0;

    int bkr = tid >> 5;
    int bnq = (tid & 31) * 4;

    int tm = (tid >> 4) << 3;
    int tn = (tid & 15) << 3;

    float acc[8][8];
    #pragma unroll
    for (int i = 0; i < 8; i++)
        #pragma unroll
        for (int j = 0; j < 8; j++) acc[i][j] = 0.f;

    for (int k0 = 0; k0 < K; k0 += 8) {
        float4 av = make_float4(0.f, 0.f, 0.f, 0.f);
        if (avalid) av = *(const float4*)(A + (size_t)arow * K + k0 + akq);
        As[akq + 0][arid] = av.x; As[akq + 1][arid] = av.y;
        As[akq + 2][arid] = av.z; As[akq + 3][arid] = av.w;

        float4 bv = *(const float4*)(Bm + (size_t)(k0 + bkr) * Nn + col0 + bnq);
        *(float4*)&Bs[bkr][bnq] = bv;
        __syncthreads();
        #pragma unroll
        for (int kk = 0; kk < 8; kk++) {
            float a8[8], b8[8];
            *(float4*)(a8)     = *(const float4*)&As[kk][tm];
            *(float4*)(a8 + 4) = *(const float4*)&As[kk][tm + 4];
            *(float4*)(b8)     = *(const float4*)&Bs[kk][tn];
            *(float4*)(b8 + 4) = *(const float4*)&Bs[kk][tn + 4];
            #pragma unroll
            for (int i = 0; i < 8; i++)
                #pragma unroll
                for (int j = 0; j < 8; j++) acc[i][j] += a8[i] * b8[j];
        }
        __syncthreads();
    }

    #pragma unroll
    for (int i = 0; i < 8; i++) {
        int r = row0 + tm + i;
        if (r >= M) break;
        size_t crow = SCATTER ? (size_t)gidx[r] : (size_t)r;
        float w = SCATTER ? wrow[r] : 1.0f;
        float* cptr = C + crow * Nn + col0 + tn;
        #pragma unroll
        for (int jj = 0; jj < 8; jj += 4) {
            float tmp[4];
            #pragma unroll
            for (int j = 0; j < 4; j++) {
                float val = acc[i][jj + j];
                int n = col0 + tn + jj + j;
                if (BIAS)  val += bias[n];
                if (CONDC) val += condc[(size_t)(r >> 8) * Nn + n];
                if (GELU)  val = gelu_f(val);
                if (RESID) val += res[(size_t)r * Nn + n];
                tmp[j] = val;
            }
            if (SCATTER) {
                float4 old = *(float4*)(cptr + jj);
                tmp[0] = old.x + w * tmp[0];
                tmp[1] = old.y + w * tmp[1];
                tmp[2] = old.z + w * tmp[2];
                tmp[3] = old.w + w * tmp[3];
            }
            *(float4*)(cptr + jj) = make_float4(tmp[0], tmp[1], tmp[2], tmp[3]);
        }
    }
}

// ---------------- attention: S = scale * Q K^T  (64x64 tiles, k=64) ----------------
__global__ __launch_bounds__(256) void attn_scores(
    const float* __restrict__ qkv, float* __restrict__ S)
{
    int kt = blockIdx.x, qt = blockIdx.y, bh = blockIdx.z;
    int b = bh >> 4, h = bh & 15;
    int q0 = qt * 64, k0 = kt * 64;
    __shared__ float Qs[64][65];
    __shared__ float Ks[64][65];
    int tid = threadIdx.x;
    #pragma unroll
    for (int i = 0; i < 4; i++) {
        int lin = tid + i * 256;
        int row = lin >> 4;
        int c4  = (lin & 15) * 4;
        float4 qv = *(const float4*)(qkv + (size_t)(b * NSEQ + q0 + row) * 3 * DIM + h * HDIM + c4);
        Qs[row][c4] = qv.x; Qs[row][c4 + 1] = qv.y; Qs[row][c4 + 2] = qv.z; Qs[row][c4 + 3] = qv.w;
        float4 kv = *(const float4*)(qkv + (size_t)(b * NSEQ + k0 + row) * 3 * DIM + DIM + h * HDIM + c4);
        Ks[row][c4] = kv.x; Ks[row][c4 + 1] = kv.y; Ks[row][c4 + 2] = kv.z; Ks[row][c4 + 3] = kv.w;
    }
    __syncthreads();
    int ty = tid >> 4, tx = tid & 15;
    float acc[4][4];
    #pragma unroll
    for (int i = 0; i < 4; i++)
        #pragma unroll
        for (int j = 0; j < 4; j++) acc[i][j] = 0.f;
    #pragma unroll 16
    for (int kk = 0; kk < 64; kk++) {
        float a[4], bv[4];
        #pragma unroll
        for (int i = 0; i < 4; i++) a[i]  = Qs[ty * 4 + i][kk];
        #pragma unroll
        for (int j = 0; j < 4; j++) bv[j] = Ks[tx * 4 + j][kk];
        #pragma unroll
        for (int i = 0; i < 4; i++)
            #pragma unroll
            for (int j = 0; j < 4; j++) acc[i][j] += a[i] * bv[j];
    }
    float* Sp = S + (size_t)bh * NSEQ * NSEQ;
    #pragma unroll
    for (int i = 0; i < 4; i++) {
        float4 v = make_float4(acc[i][0] * 0.125f, acc[i][1] * 0.125f,
                               acc[i][2] * 0.125f, acc[i][3] * 0.125f);
        *(float4*)(Sp + (size_t)(q0 + ty * 4 + i) * NSEQ + k0 + tx * 4) = v;
    }
}

// ---------------- softmax over rows of 256 (one warp/row) ----------------
__global__ __launch_bounds__(128) void softmax_kernel(float* __restrict__ S) {
    size_t row = (size_t)blockIdx.x * 4 + (threadIdx.x >> 5);
    int lane = threadIdx.x & 31;
    float* p = S + row * NSEQ;
    float v[8];
    float m = -1e30f;
    #pragma unroll
    for (int i = 0; i < 8; i++) { v[i] = p[lane + i * 32]; m = fmaxf(m, v[i]); }
    m = warpmax(m);
    float s = 0.f;
    #pragma unroll
    for (int i = 0; i < 8; i++) { v[i] = expf(v[i] - m); s += v[i]; }
    s = warpsum(s);
    float inv = 1.0f / s;
    #pragma unroll
    for (int i = 0; i < 8; i++) p[lane + i * 32] = v[i] * inv;
}

// ---------------- O = P @ V  (64 q-rows x 64 cols per block) ----------------
__global__ __launch_bounds__(256) void attn_av(
    const float* __restrict__ qkv, const float* __restrict__ S, float* __restrict__ o)
{
    int qt = blockIdx.x, bh = blockIdx.y;
    int b = bh >> 4, h = bh & 15;
    int q0 = qt * 64;
    __shared__ float Ps[64][17];
    __shared__ float Vs[16][64];
    int tid = threadIdx.x;
    int ty = tid >> 4, tx = tid & 15;
    float acc[4][4];
    #pragma unroll
    for (int i = 0; i < 4; i++)
        #pragma unroll
        for (int j = 0; j < 4; j++) acc[i][j] = 0.f;
    const float* Sp = S + (size_t)bh * NSEQ * NSEQ;
    for (int k0 = 0; k0 < NSEQ; k0 += 16) {
        {
            int row = tid >> 2, c = (tid & 3) * 4;
            float4 pv = *(const float4*)(Sp + (size_t)(q0 + row) * NSEQ + k0 + c);
            Ps[row][c] = pv.x; Ps[row][c + 1] = pv.y; Ps[row][c + 2] = pv.z; Ps[row][c + 3] = pv.w;
        }
        {
            int kr = tid >> 4, c = (tid & 15) * 4;
            float4 vv = *(const float4*)(qkv + (size_t)(b * NSEQ + k0 + kr) * 3 * DIM + 2 * DIM + h * HDIM + c);
            *(float4*)&Vs[kr][c] = vv;
        }
        __syncthreads();
        #pragma unroll
        for (int kk = 0; kk < 16; kk++) {
            float a[4], bv[4];
            #pragma unroll
            for (int i = 0; i < 4; i++) a[i]  = Ps[ty * 4 + i][kk];
            #pragma unroll
            for (int j = 0; j < 4; j++) bv[j] = Vs[kk][tx * 4 + j];
            #pragma unroll
            for (int i = 0; i < 4; i++)
                #pragma unroll
                for (int j = 0; j < 4; j++) acc[i][j] += a[i] * bv[j];
        }
        __syncthreads();
    }
    #pragma unroll
    for (int i = 0; i < 4; i++) {
        float4 v = make_float4(acc[i][0], acc[i][1], acc[i][2], acc[i][3]);
        *(float4*)(o + (size_t)(b * NSEQ + q0 + ty * 4 + i) * DIM + h * HDIM + tx * 4) = v;
    }
}

// ---------------- router fc2 + softmax + top2 + scatter lists ----------------
__global__ __launch_bounds__(128) void router_kernel(
    const float* __restrict__ gh, const float* __restrict__ W, const float* __restrict__ bias)
{
    int t = blockIdx.x;
    int wid = threadIdx.x >> 5, lane = threadIdx.x & 31;
    const float* row = gh + (size_t)t * RHC;
    float s = 0.f;
    for (int k = lane; k < RHC; k += 32) s += row[k] * W[k * NE + wid];
    s = warpsum(s);
    __shared__ float logits[NE];
    if (lane == 0) logits[wid] = s + bias[wid];
    __syncthreads();
    if (threadIdx.x == 0) {
        float l[NE], m = -1e30f;
        #pragma unroll
        for (int e = 0; e < NE; e++) { l[e] = logits[e]; m = fmaxf(m, l[e]); }
        float ssum = 0.f;
        #pragma unroll
        for (int e = 0; e < NE; e++) { l[e] = expf(l[e] - m); ssum += l[e]; }
        float p[NE];
        #pragma unroll
        for (int e = 0; e < NE; e++)
            p[e] = fminf(fmaxf(l[e] / ssum, 1e-9f), 1.0f - 1e-9f);
        int i1 = 0;
        #pragma unroll
        for (int e = 1; e < NE; e++) if (p[e] > p[i1]) i1 = e;
        int i2 = -1;
        #pragma unroll
        for (int e = 0; e < NE; e++) {
            if (e == i1) continue;
            if (i2 < 0 || p[e] > p[i2]) i2 = e;
        }
        float wsum = p[i1] + p[i2];
        int pos = atomicAdd(&g_cnt[i1], 1);
        g_idx[i1 * TT + pos] = t; g_wgt[i1 * TT + pos] = p[i1] / wsum;
        pos = atomicAdd(&g_cnt[i2], 1);
        g_idx[i2 * TT + pos] = t; g_wgt[i2 * TT + pos] = p[i2] / wsum;
    }
}

__global__ void zero_cnt_kernel() {
    if (threadIdx.x < NE) g_cnt[threadIdx.x] = 0;
}

__global__ __launch_bounds__(256) void copy_kernel(const float* __restrict__ a, float* __restrict__ b) {
    size_t i = (size_t)blockIdx.x * blockDim.x + threadIdx.x;
    ((float4*)b)[i] = ((const float4*)a)[i];
}

// ---------------- host launcher ----------------
static void* symaddr(const void* s) {
    void* p = nullptr;
    cudaGetSymbolAddress(&p, s);
    return p;
}

extern "C" void kernel_launch(void* const* d_in, const int* in_sizes, int n_in,
                              void* d_out, int out_size) {
    const float* x       = (const float*)d_in[0];
    const float* cond    = (const float*)d_in[1];
    const float* ln1_g   = (const float*)d_in[2];
    const float* ln1_b   = (const float*)d_in[3];
    const float* qkv_w   = (const float*)d_in[4];
    const float* proj_w  = (const float*)d_in[5];
    const float* proj_b  = (const float*)d_in[6];
    const float* ln2_g   = (const float*)d_in[7];
    const float* ln2_b   = (const float*)d_in[8];
    const float* r_fc1_w = (const float*)d_in[9];
    const float* r_fc1_b = (const float*)d_in[10];
    const float* r_fc2_w = (const float*)d_in[11];
    const float* r_fc2_b = (const float*)d_in[12];
    const float* e_w1    = (const float*)d_in[13];
    const float* e_b1    = (const float*)d_in[14];
    const float* e_w2    = (const float*)d_in[15];
    const float* e_b2    = (const float*)d_in[16];
    float* out = (float*)d_out;

    float* h1    = (float*)symaddr(g_h1);
    float* qkv   = (float*)symaddr(g_qkv);
    float* S     = (float*)symaddr(g_S);
    float* o     = (float*)symaddr(g_o);
    float* x1    = (float*)symaddr(g_x1);
    float* h2    = (float*)symaddr(g_h2);
    float* condc = (float*)symaddr(g_condc);
    float* gh    = (float*)symaddr(g_gh);
    float* hid   = (float*)symaddr(g_hid);
    int*   cnt   = (int*)symaddr(g_cnt);
    int*   idx   = (int*)symaddr(g_idx);
    float* wgt   = (float*)symaddr(g_wgt);

    zero_cnt_kernel<<<1, 32>>>();

    // LN1
    ln_kernel<<<TT, 256>>>(x, ln1_g, ln1_b, h1);

    // QKV = h1 @ qkv_w   [8192,3072]
    gemm_kernel<false,false,false,false,false,false>
        <<<dim3(3 * DIM / 128, TT / 128), 256>>>(h1, qkv_w, qkv, TT, 3 * DIM, DIM,
            nullptr, nullptr, nullptr, nullptr, nullptr, nullptr);

    // attention
    attn_scores<<<dim3(4, 4, BB * NH), 256>>>(qkv, S);
    softmax_kernel<<<BB * NH * NSEQ / 4, 128>>>(S);
    attn_av<<<dim3(4, BB * NH), 256>>>(qkv, S, o);

    // x1 = x + o @ proj_w + proj_b
    gemm_kernel<false,false,true,false,true,false>
        <<<dim3(DIM / 128, TT / 128), 256>>>(o, proj_w, x1, TT, DIM, DIM,
            proj_b, x, nullptr, nullptr, nullptr, nullptr);

    // LN2
    ln_kernel<<<TT, 256>>>(x1, ln2_g, ln2_b, h2);

    // condc[b] = cond[b] @ r_fc1_w[D:, :]   [32,2048]
    gemm_kernel<false,false,false,false,false,false>
        <<<dim3(RHC / 128, 1), 256>>>(cond, r_fc1_w + (size_t)DIM * RHC, condc,
            BB, RHC, CDIM, nullptr, nullptr, nullptr, nullptr, nullptr, nullptr);

    // gh = gelu(h2 @ r_fc1_w[:D] + condc[b] + b1)
    gemm_kernel<false,false,true,true,false,true>
        <<<dim3(RHC / 128, TT / 128), 256>>>(h2, r_fc1_w, gh, TT, RHC, DIM,
            r_fc1_b, nullptr, condc, nullptr, nullptr, nullptr);

    // router: fc2 + softmax + top2 + per-expert lists
    router_kernel<<<TT, 128>>>(gh, r_fc2_w, r_fc2_b);

    // out = x1
    copy_kernel<<<TT * DIM / 4 / 256, 256>>>(x1, out);

    // experts: gather rows of h2 -> hid = gelu(. @ w1 + b1); out[tok] += w * (hid @ w2 + b2)
    for (int e = 0; e < NE; e++) {
        gemm_kernel<true,false,true,true,false,false>
            <<<dim3(DFFC / 128, TT / 128), 256>>>(h2, e_w1 + (size_t)e * DIM * DFFC, hid,
                TT, DFFC, DIM, e_b1 + e * DFFC, nullptr, nullptr,
                idx + e * TT, nullptr, cnt + e);
        gemm_kernel<false,true,true,false,false,false>
            <<<dim3(DIM / 128, TT / 128), 256>>>(hid, e_w2 + (size_t)e * DFFC * DIM, out,
                TT, DIM, DFFC, e_b2 + e * DIM, nullptr, nullptr,
                idx + e * TT, wgt + e * TT, cnt + e);
    }
}